// round 17
// baseline (speedup 1.0000x reference)
#include <cuda_runtime.h>
#include <cuda_fp16.h>
#include <cstdint>
#include <cstddef>

#define TPB     512           // warps 0-7 = MMA (N=64 each), warps 8-15 = activation
#define MB      16
#define TSTEPS  512
#define ISZ     5
#define TI      (TSTEPS*ISZ)
#define HID     128
#define KTOT    144
#define WSTR    152           // halves per A/B row (304B: ldmatrix conflict-free)
#define GH      136           // halves per gate-plane row

#define B_BYTES   (512*WSTR*2)        // 155648
#define A_BYTES   (MB*WSTR*2)         // 4864 per buffer
#define G_BYTES   (4*16*GH*2)         // 17408 (fp16 gates, 4 planes)
#define SMEM_B    0
#define SMEM_A0   B_BYTES
#define SMEM_A1   (SMEM_A0 + A_BYTES)
#define SMEM_G    (SMEM_A1 + A_BYTES)
#define SMEM_TOTAL (SMEM_G + G_BYTES) // 182784

#define CNT_CH  288           // 32 act arrive + 256 MMA sync
#define CNT_ALL 512

__device__ __forceinline__ uint32_t smem_u32(const void* p) {
    uint32_t a;
    asm("{ .reg .u64 t; cvta.to.shared.u64 t, %1; cvt.u32.u64 %0, t; }" : "=r"(a) : "l"(p));
    return a;
}
#define LDSM4(r0, r1, r2, r3, addr) \
    asm volatile("ldmatrix.sync.aligned.m8n8.x4.shared.b16 {%0,%1,%2,%3}, [%4];" \
        : "=r"(r0), "=r"(r1), "=r"(r2), "=r"(r3) : "r"(addr))
#define MMA16816(d, a0, a1, a2, a3, b0, b1) \
    asm volatile("mma.sync.aligned.m16n8k16.row.col.f32.f16.f16.f32 " \
        "{%0,%1,%2,%3}, {%4,%5,%6,%7}, {%8,%9}, {%0,%1,%2,%3};" \
        : "+f"((d)[0]), "+f"((d)[1]), "+f"((d)[2]), "+f"((d)[3]) \
        : "r"(a0), "r"(a1), "r"(a2), "r"(a3), "r"(b0), "r"(b1))
#define BSYNC(id, cnt)   asm volatile("bar.sync %0, %1;"   :: "r"(id), "r"(cnt) : "memory")
#define BARRIVE(id, cnt) asm volatile("bar.arrive %0, %1;" :: "r"(id), "r"(cnt) : "memory")
#define MEMBAR() asm volatile("membar.cta;" ::: "memory")

__device__ __forceinline__ float tanha(float x) {
    float r; asm("tanh.approx.f32 %0, %1;" : "=f"(r) : "f"(x)); return r;
}
__device__ __forceinline__ float siga(float x) {
    return fmaf(0.5f, tanha(0.5f * x), 0.5f);
}

__global__ void __launch_bounds__(TPB, 1)
lstm_ws(const float* __restrict__ x,     const float* __restrict__ W_ih,
        const float* __restrict__ W_hh,  const float* __restrict__ b_ih,
        const float* __restrict__ b_hh,  const float* __restrict__ W_lin,
        const float* __restrict__ b_lin, float* __restrict__ out)
{
    extern __shared__ char smem[];
    const uint32_t sb = smem_u32(smem);
    const int tid = threadIdx.x;
    const int w = tid >> 5, l = tid & 31;
    const int b0 = blockIdx.x * MB;

    // ---- stage B = W, fp16 [ni][k]; ni = 64*wm + 16*g + jj (wm = n-warp) ----
    for (int e = tid; e < 512 * KTOT; e += TPB) {
        int ni = e / KTOT, k = e - ni * KTOT;
        int wm = ni >> 6, rem = ni & 63;
        int g = rem >> 4, jj = rem & 15;
        int nsrc = g * HID + wm * 16 + jj;
        float v = 0.f;
        if (k < HID)        v = W_hh[nsrc * HID + k];
        else if (k < 133)   v = W_ih[nsrc * ISZ + (k - HID)];
        else if (k == 133)  v = b_ih[nsrc] + b_hh[nsrc];
        *reinterpret_cast<__half*>(smem + SMEM_B + (size_t)(ni * WSTR + k) * 2) = __float2half(v);
    }
    __syncthreads();

    // ---- init A buffers: zero, bias col (both), x(t=0) into buffer 0 ----
    for (int i = tid; i < 2 * A_BYTES / 4; i += TPB)
        reinterpret_cast<uint32_t*>(smem + SMEM_A0)[i] = 0u;
    __syncthreads();
    if (tid < MB) {
        *reinterpret_cast<__half*>(smem + SMEM_A0 + (tid * WSTR + 133) * 2) = __float2half(1.f);
        *reinterpret_cast<__half*>(smem + SMEM_A1 + (tid * WSTR + 133) * 2) = __float2half(1.f);
    }
    if (tid < MB * ISZ) {
        int r = tid / ISZ, i = tid - r * ISZ;
        *reinterpret_cast<__half*>(smem + SMEM_A0 + (r * WSTR + HID + i) * 2) =
            __float2half(x[(size_t)(b0 + r) * TI + i]);
    }
    __syncthreads();

    if (w < 8) {
        // ======== MMA warps: N=64 (4 gates x 16 cols), M=16, K=9 chunks ========
        const int q = l >> 2, m = l & 3;
        const uint32_t b_base = sb + SMEM_B +
            (uint32_t)(((64 * w + ((l >> 4) & 1) * 8 + (l & 7)) * WSTR + ((l >> 3) & 1) * 8) * 2);
        const uint32_t a_lane0 = sb + SMEM_A0 +
            (uint32_t)(((((l >> 3) & 1) * 8 + (l & 7)) * WSTR + ((l >> 4) & 1) * 8) * 2);
        const uint32_t a_lane1 = a_lane0 + A_BYTES;

        // hoist B chunks 0-3: Bq[ch][g*4 + {n0-7 klo, n0-7 khi, n8-15 klo, n8-15 khi}]
        uint32_t Bq[4][16];
        #pragma unroll
        for (int ch = 0; ch < 4; ch++)
            #pragma unroll
            for (int g = 0; g < 4; g++)
                LDSM4(Bq[ch][4*g], Bq[ch][4*g+1], Bq[ch][4*g+2], Bq[ch][4*g+3],
                      b_base + (uint32_t)(g * (16 * WSTR * 2) + ch * 32));

        __half* Gp = reinterpret_cast<__half*>(smem + SMEM_G);

        for (int t = 0; t < TSTEPS; t++) {
            const uint32_t Ard = (t & 1) ? a_lane1 : a_lane0;
            float C[4][8];
            #pragma unroll
            for (int g = 0; g < 4; g++)
                #pragma unroll
                for (int u = 0; u < 8; u++) C[g][u] = 0.f;

            #pragma unroll
            for (int ch = 0; ch < 8; ch++) {
                uint32_t Bt[16];
                if (ch >= 4) {     // load B before the barrier (static region)
                    #pragma unroll
                    for (int g = 0; g < 4; g++)
                        LDSM4(Bt[4*g], Bt[4*g+1], Bt[4*g+2], Bt[4*g+3],
                              b_base + (uint32_t)(g * (16 * WSTR * 2) + ch * 32));
                }
                BSYNC(1 + ch, CNT_CH);          // h cols [16ch,16ch+16) ready
                uint32_t a0, a1, a2, a3;
                LDSM4(a0, a1, a2, a3, Ard + ch * 32);
                #pragma unroll
                for (int g = 0; g < 4; g++) {
                    const uint32_t* B8 = (ch < 4) ? &Bq[ch][4*g] : &Bt[4*g];
                    MMA16816(&C[g][0], a0, a1, a2, a3, B8[0], B8[1]);
                    MMA16816(&C[g][4], a0, a1, a2, a3, B8[2], B8[3]);
                }
            }
            {   // x/bias chunk (ch 8)
                uint32_t Bt[16];
                #pragma unroll
                for (int g = 0; g < 4; g++)
                    LDSM4(Bt[4*g], Bt[4*g+1], Bt[4*g+2], Bt[4*g+3],
                          b_base + (uint32_t)(g * (16 * WSTR * 2) + 8 * 32));
                BSYNC(9, CNT_ALL);
                uint32_t a0, a1, a2, a3;
                LDSM4(a0, a1, a2, a3, Ard + 8 * 32);
                #pragma unroll
                for (int g = 0; g < 4; g++) {
                    MMA16816(&C[g][0], a0, a1, a2, a3, Bt[4*g],   Bt[4*g+1]);
                    MMA16816(&C[g][4], a0, a1, a2, a3, Bt[4*g+2], Bt[4*g+3]);
                }
            }

            BSYNC(11, CNT_ALL);                 // G buffer free
            #pragma unroll
            for (int g = 0; g < 4; g++) {
                #pragma unroll
                for (int tt = 0; tt < 2; tt++) {
                    __half2 hlo = __floats2half2_rn(C[g][4*tt + 0], C[g][4*tt + 1]);
                    __half2 hhi = __floats2half2_rn(C[g][4*tt + 2], C[g][4*tt + 3]);
                    int cbase = 16 * w + 8 * tt + 2 * m;
                    *reinterpret_cast<__half2*>(&Gp[(g * 16 + q)     * GH + cbase]) = hlo;
                    *reinterpret_cast<__half2*>(&Gp[(g * 16 + q + 8) * GH + cbase]) = hhi;
                }
            }
            MEMBAR();
            BARRIVE(10, CNT_ALL);               // gates(t) ready
        }
    } else {
        // ======== activation warps: warp w handles h-chunk (15-w) ========
        const int ch  = 15 - w;                 // warp 15 -> chunk 0 (issues first)
        const int r   = l >> 1;                 // batch row 0..15
        const int hf  = l & 1;
        const int c0  = 16 * ch + 8 * hf;       // this thread's 8 h-cols
        const int aidx = tid - 256;
        const bool xduty = (aidx < MB * ISZ);
        const int xr = aidx / ISZ, xi = aidx - xr * ISZ;
        const __half* Gp = reinterpret_cast<const __half*>(smem + SMEM_G);
        const int mybar = 1 + ch;

        float c_st[8];
        #pragma unroll
        for (int u = 0; u < 8; u++) c_st[u] = 0.f;

        // prologue arming (A buffer 0 + G-free count as produced)
        BARRIVE(mybar, CNT_CH);
        BARRIVE(9, CNT_ALL);
        BARRIVE(11, CNT_ALL);

        for (int t = 0; t < TSTEPS; t++) {
            float xv = 0.f;
            const bool dox = xduty && (t + 1 < TSTEPS);
            if (dox) xv = x[(size_t)(b0 + xr) * TI + (size_t)(t + 1) * ISZ + xi];

            BSYNC(10, CNT_ALL);                 // gates(t) ready
            // read this thread's gates (fp16, 1 LDS.128 per plane)
            float gi[8], gf[8], gg[8], go[8];
            #pragma unroll
            for (int g = 0; g < 4; g++) {
                uint4 v = *reinterpret_cast<const uint4*>(&Gp[(g * 16 + r) * GH + c0]);
                float* dst = (g == 0) ? gi : (g == 1) ? gf : (g == 2) ? gg : go;
                float2 p0 = __half22float2(*reinterpret_cast<const __half2*>(&v.x));
                float2 p1 = __half22float2(*reinterpret_cast<const __half2*>(&v.y));
                float2 p2 = __half22float2(*reinterpret_cast<const __half2*>(&v.z));
                float2 p3 = __half22float2(*reinterpret_cast<const __half2*>(&v.w));
                dst[0] = p0.x; dst[1] = p0.y; dst[2] = p1.x; dst[3] = p1.y;
                dst[4] = p2.x; dst[5] = p2.y; dst[6] = p3.x; dst[7] = p3.y;
            }
            float hv[8];
            #pragma unroll
            for (int u = 0; u < 8; u++) {
                float cc = fmaf(siga(gf[u]), c_st[u], siga(gi[u]) * tanha(gg[u]));
                c_st[u] = cc;
                hv[u] = siga(go[u]) * tanha(cc);
            }
            char* Awb = smem + SMEM_A0 + (((t + 1) & 1) ? A_BYTES : 0);
            uint4 pk;
            {
                __half2 h0 = __floats2half2_rn(hv[0], hv[1]);
                __half2 h1 = __floats2half2_rn(hv[2], hv[3]);
                __half2 h2 = __floats2half2_rn(hv[4], hv[5]);
                __half2 h3 = __floats2half2_rn(hv[6], hv[7]);
                pk.x = *reinterpret_cast<uint32_t*>(&h0);
                pk.y = *reinterpret_cast<uint32_t*>(&h1);
                pk.z = *reinterpret_cast<uint32_t*>(&h2);
                pk.w = *reinterpret_cast<uint32_t*>(&h3);
            }
            *reinterpret_cast<uint4*>(Awb + r * (WSTR * 2) + c0 * 2) = pk;
            if (dox)
                *reinterpret_cast<__half*>(Awb + xr * (WSTR * 2) + (HID + xi) * 2) =
                    __float2half_rn(xv);
            MEMBAR();
            BARRIVE(mybar, CNT_CH);             // my h-chunk(t+1) ready
            BARRIVE(9, CNT_ALL);                // x/bias ready
            BARRIVE(11, CNT_ALL);               // done reading G(t)
        }
    }

    __syncthreads();
    // ---- epilogue: final h(511) is in buffer 0 ----
    if (tid < 128) {
        const int row = tid >> 3, seg = tid & 7;
        const __half* Hf = reinterpret_cast<const __half*>(smem + SMEM_A0);
        float s = 0.f;
        #pragma unroll
        for (int jj = 0; jj < 16; jj++) {
            int j = seg * 16 + jj;
            s += __half2float(Hf[row * WSTR + j]) * W_lin[j];
        }
        s += __shfl_xor_sync(0xffffffffu, s, 4);
        s += __shfl_xor_sync(0xffffffffu, s, 2);
        s += __shfl_xor_sync(0xffffffffu, s, 1);
        if (seg == 0) out[b0 + row] = s + b_lin[0];
    }
}

extern "C" void kernel_launch(void* const* d_in, const int* in_sizes, int n_in,
                              void* d_out, int out_size) {
    const float* x     = (const float*)d_in[0];
    const float* W_ih  = (const float*)d_in[1];
    const float* W_hh  = (const float*)d_in[2];
    const float* b_ih  = (const float*)d_in[3];
    const float* b_hh  = (const float*)d_in[4];
    const float* W_lin = (const float*)d_in[5];
    const float* b_lin = (const float*)d_in[6];
    float* out = (float*)d_out;

    int B    = in_sizes[0] / TI;   // 2048
    int nCTA = B / MB;             // 128 CTAs, one wave

    cudaFuncSetAttribute(lstm_ws,
                         cudaFuncAttributeMaxDynamicSharedMemorySize, SMEM_TOTAL);
    lstm_ws<<<nCTA, TPB, SMEM_TOTAL>>>(x, W_ih, W_hh, b_ih, b_hh,
                                       W_lin, b_lin, out);
}